// round 12
// baseline (speedup 1.0000x reference)
#include <cuda_runtime.h>

// ---------------------------------------------------------------------------
// CorrelationPyramid: proj(1x1 conv C=128->64) -> pyramid avg-pool ->
// L2-normalized banded circular correlation at 4 levels.
// Scratch features channel-planar [img][c][h][w]; img 0..1 = q batches,
// 2..9 = v (b*4+n). Normalization folded into epilogue via inverse norms.
// R12: proj reads W via uniform-broadcast __ldg from pre-transposed g_Wt
// (kills the 8192-wavefront per-block staging). corr<4> in ncu slot 4.
// ---------------------------------------------------------------------------

#define HW0 25600   // 160*160

typedef unsigned long long u64;

__device__ float g_F0[10 * 64 * 25600];
__device__ float g_F1[10 * 64 * 6400];
__device__ float g_F2[10 * 64 * 1600];
__device__ float g_F3[10 * 64 * 400];
__device__ float g_I0[10 * 25600];
__device__ float g_I1[10 * 6400];
__device__ float g_I2[10 * 1600];
__device__ float g_I3[10 * 400];
__device__ __align__(16) float g_Wt[8192];   // Wt[c*64+o] = pw[o*128+c]

__device__ __forceinline__ u64 pack2(float lo, float hi) {
  u64 r;
  asm("mov.b64 %0, {%1, %2};" : "=l"(r) : "f"(lo), "f"(hi));
  return r;
}
__device__ __forceinline__ float2 unpack2(u64 v) {
  float2 f;
  asm("mov.b64 {%0, %1}, %2;" : "=f"(f.x), "=f"(f.y) : "l"(v));
  return f;
}
__device__ __forceinline__ void ffma2(u64& d, u64 a, u64 b) {
  asm("fma.rn.f32x2 %0, %1, %2, %0;" : "+l"(d) : "l"(a), "l"(b));
}

// ---------------------------------------------------------------------------
// One-off W transpose (32 KB): strided read, coalesced write. Runs once.
// ---------------------------------------------------------------------------
__global__ void wtrans_kernel(const float* __restrict__ pw) {
  int i = blockIdx.x * 256 + threadIdx.x;   // 8192 threads
  g_Wt[i] = pw[(i & 63) * 128 + (i >> 6)];
}

// ---------------------------------------------------------------------------
// Projection + fused level-0 inverse-norm (FFMA2 on output pairs).
// W read in the mainloop via uniform-address __ldg (L1-resident broadcast);
// no smem W staging at all.
// ---------------------------------------------------------------------------
__global__ __launch_bounds__(256, 3) void proj_kernel(
    const float* __restrict__ qf, const float* __restrict__ vf,
    const float* __restrict__ pb) {
  __shared__ float Bsh[64];
  __shared__ __align__(16) float Xs[16][128];

  const int img = blockIdx.y;
  const float* src = (img < 2) ? qf + (size_t)img * 128 * HW0
                               : vf + (size_t)(img - 2) * 128 * HW0;
  float* dst = g_F0 + (size_t)img * 64 * HW0;

  const int t = threadIdx.x;
  if (t < 64) Bsh[t] = pb[t];

  const int og = t >> 5;
  const int lane = t & 31;
  const int pxb = blockIdx.x * 128;
  const int px = lane * 4;

  u64 acc2[4][4];
#pragma unroll
  for (int o = 0; o < 4; o++)
#pragma unroll
    for (int i = 0; i < 4; i++) acc2[o][i] = 0ull;

  float4 pre[2];
  {
    int i0 = t * 2, i1 = t * 2 + 1;
    pre[0] = *reinterpret_cast<const float4*>(
        src + (size_t)(i0 >> 5) * HW0 + pxb + (i0 & 31) * 4);
    pre[1] = *reinterpret_cast<const float4*>(
        src + (size_t)(i1 >> 5) * HW0 + pxb + (i1 & 31) * 4);
  }

  for (int ch = 0; ch < 8; ch++) {
    __syncthreads();
#pragma unroll
    for (int j = 0; j < 2; j++) {
      int idx = t * 2 + j;
      *reinterpret_cast<float4*>(&Xs[idx >> 5][(idx & 31) * 4]) = pre[j];
    }
    __syncthreads();
    if (ch < 7) {
#pragma unroll
      for (int j = 0; j < 2; j++) {
        int idx = t * 2 + j;
        pre[j] = *reinterpret_cast<const float4*>(
            src + (size_t)((ch + 1) * 16 + (idx >> 5)) * HW0 + pxb + (idx & 31) * 4);
      }
    }
#pragma unroll
    for (int c = 0; c < 16; c++) {
      const ulonglong2* wp = reinterpret_cast<const ulonglong2*>(
          g_Wt + (ch * 16 + c) * 64 + og * 8);
      ulonglong2 wA = __ldg(wp);       // uniform per warp: 1-sector broadcast
      ulonglong2 wB = __ldg(wp + 1);
      float4 x = *reinterpret_cast<const float4*>(&Xs[c][px]);
      u64 xp[4] = {pack2(x.x, x.x), pack2(x.y, x.y), pack2(x.z, x.z),
                   pack2(x.w, x.w)};
#pragma unroll
      for (int i = 0; i < 4; i++) {
        ffma2(acc2[0][i], wA.x, xp[i]);
        ffma2(acc2[1][i], wA.y, xp[i]);
        ffma2(acc2[2][i], wB.x, xp[i]);
        ffma2(acc2[3][i], wB.y, xp[i]);
      }
    }
  }

  float ps[4] = {0.f, 0.f, 0.f, 0.f};
#pragma unroll
  for (int o2 = 0; o2 < 4; o2++) {
    int o0 = og * 8 + 2 * o2;
    float b0 = Bsh[o0], b1 = Bsh[o0 + 1];
    float y0[4], y1[4];
#pragma unroll
    for (int i = 0; i < 4; i++) {
      float2 y = unpack2(acc2[o2][i]);
      y0[i] = y.x + b0;
      y1[i] = y.y + b1;
      ps[i] += y0[i] * y0[i] + y1[i] * y1[i];
    }
    float4 r0 = {y0[0], y0[1], y0[2], y0[3]};
    float4 r1 = {y1[0], y1[1], y1[2], y1[3]};
    *reinterpret_cast<float4*>(dst + (size_t)o0 * HW0 + pxb + px) = r0;
    *reinterpret_cast<float4*>(dst + (size_t)(o0 + 1) * HW0 + pxb + px) = r1;
  }

  float* red = &Xs[0][0];
  __syncthreads();
  *reinterpret_cast<float4*>(&red[og * 128 + px]) =
      make_float4(ps[0], ps[1], ps[2], ps[3]);
  __syncthreads();
  if (t < 128) {
    float s = 0.f;
#pragma unroll
    for (int w = 0; w < 8; w++) s += red[w * 128 + t];
    g_I0[(size_t)img * HW0 + pxb + t] = 1.f / fmaxf(sqrtf(s), 1e-12f);
  }
}

// ---------------------------------------------------------------------------
// 2x2 avg pool.
// ---------------------------------------------------------------------------
__global__ __launch_bounds__(256) void pool_kernel(
    const float* __restrict__ in, float* __restrict__ out,
    int Hin, int Win, int total2) {
  int idx = blockIdx.x * 256 + threadIdx.x;
  if (idx >= total2) return;
  int Wo = Win >> 1, Ho = Hin >> 1;
  int w2 = Wo >> 1;
  int x2 = idx % w2;
  int rest = idx / w2;
  int y = rest % Ho;
  int plane = rest / Ho;
  const float* p = in + (size_t)plane * Hin * Win + (size_t)(2 * y) * Win + 4 * x2;
  float4 a = *reinterpret_cast<const float4*>(p);
  float4 b = *reinterpret_cast<const float4*>(p + Win);
  float2 o;
  o.x = 0.25f * (a.x + a.y + b.x + b.y);
  o.y = 0.25f * (a.z + a.w + b.z + b.w);
  *reinterpret_cast<float2*>(out + (size_t)plane * Ho * Wo + (size_t)y * Wo + 2 * x2) = o;
}

// ---------------------------------------------------------------------------
// Per-pixel inverse L2 norm over 64 channels (levels 1..3).
// ---------------------------------------------------------------------------
__global__ __launch_bounds__(256) void invnorm_kernel(
    const float* __restrict__ F, float* __restrict__ I, int HW, int total) {
  int idx = blockIdx.x * 256 + threadIdx.x;
  if (idx >= total) return;
  int img = idx / HW;
  int p = idx - img * HW;
  const float* f = F + (size_t)img * 64 * HW + p;
  float s = 0.f;
#pragma unroll
  for (int c = 0; c < 64; c++) {
    float v = f[(size_t)c * HW];
    s += v * v;
  }
  I[idx] = 1.f / fmaxf(sqrtf(s), 1e-12f);
}

// ---------------------------------------------------------------------------
// Banded circular correlation, radius R (direct banded STG).
// Tile: 4 rows x 32 cols. Block: NW warps (warp <-> dy). Thread: 4 px x NW dx.
// ---------------------------------------------------------------------------
template <int R, int MINB>
__global__ __launch_bounds__(32 * (2 * R + 1), MINB) void corr_kernel(
    const float* __restrict__ F, const float* __restrict__ I,
    float* __restrict__ out, int H, int W) {
  constexpr int NW = 2 * R + 1;
  constexpr int VH = 4 + 2 * R;
  constexpr int VW = ((32 + 2 * R + 7) & ~3);
  constexpr int NV4 = (4 + 2 * R + 3) / 4;
  constexpr int NT = NW * 32;

  __shared__ __align__(16) float qs[16][4][32];
  __shared__ __align__(16) float vs[16][VH][VW];
  __shared__ float ivs[VH][VW];

  const int bn = blockIdx.z;
  const int b = bn >> 2;
  const int HWl = H * W;
  const float* Fq = F + (size_t)b * 64 * HWl;
  const float* Fv = F + (size_t)(2 + bn) * 64 * HWl;
  const float* Iq = I + (size_t)b * HWl;
  const float* Iv = I + (size_t)(2 + bn) * HWl;

  const int tx = blockIdx.x * 32, ty = blockIdx.y * 4;
  const int t = threadIdx.x, lane = t & 31, warp = t >> 5;
  const int dy = warp - R;
  const int prow = lane >> 3;         // 0..3
  const int pc = (lane & 7) * 4;      // 0,4,..,28
  const int vr = prow + R - dy;

  for (int i = t; i < VH * VW; i += NT) {
    int r = i / VW, c = i - r * VW;
    int h = ty + r - R; if (h < 0) h += H; if (h >= H) h -= H;
    int w = tx + c - R; if (w < 0) w += W; if (w >= W) w -= W;
    ivs[r][c] = Iv[h * W + w];
  }

  float acc[4][NW];
#pragma unroll
  for (int i = 0; i < 4; i++)
#pragma unroll
    for (int k = 0; k < NW; k++) acc[i][k] = 0.f;

  for (int st = 0; st < 4; st++) {
    __syncthreads();
    // stage q: 16 ch x 4 rows x 32 cols
    for (int i = t; i < 2048; i += NT) {
      int col = i & 31, r = (i >> 5) & 3, c = i >> 7;
      int w = tx + col;
      qs[c][r][col] = (w < W)
          ? Fq[(size_t)(st * 16 + c) * HWl + (ty + r) * W + w] : 0.f;
    }
    // stage v halo: 16 ch x VH x VW, circular wrap
    for (int i = t; i < 16 * VH * VW; i += NT) {
      int c = i / (VH * VW), rem = i - c * (VH * VW);
      int r = rem / VW, col = rem - r * VW;
      int h = ty + r - R; if (h < 0) h += H; if (h >= H) h -= H;
      int w = tx + col - R; if (w < 0) w += W; if (w >= W) w -= W;
      vs[c][r][col] = Fv[(size_t)(st * 16 + c) * HWl + h * W + w];
    }
    __syncthreads();

#pragma unroll
    for (int c = 0; c < 16; c++) {
      float4 q = *reinterpret_cast<const float4*>(&qs[c][prow][pc]);
      float qa[4] = {q.x, q.y, q.z, q.w};
      float vwin[NV4 * 4];
#pragma unroll
      for (int j = 0; j < NV4; j++)
        *reinterpret_cast<float4*>(&vwin[4 * j]) =
            *reinterpret_cast<const float4*>(&vs[c][vr][pc + 4 * j]);
#pragma unroll
      for (int k = 0; k < NW; k++) {
#pragma unroll
        for (int i = 0; i < 4; i++)
          acc[i][k] += qa[i] * vwin[i + 2 * R - k];
      }
    }
  }

  const int h = ty + prow;
#pragma unroll
  for (int i = 0; i < 4; i++) {
    const int w = tx + pc + i;
    if (w >= W) continue;
    const float qi = Iq[h * W + w];
    float* op = out + ((size_t)(bn * H + h) * W + w) * (NW * NW) + (dy + R) * NW;
#pragma unroll
    for (int k = 0; k < NW; k++)
      op[k] = acc[i][k] * qi * ivs[vr][pc + i + 2 * R - k];
  }
}

// ---------------------------------------------------------------------------

extern "C" void kernel_launch(void* const* d_in, const int* in_sizes, int n_in,
                              void* d_out, int out_size) {
  const float* qf = (const float*)d_in[0];   // [2,128,160,160]
  const float* vf = (const float*)d_in[1];   // [2,4,128,160,160]
  const float* pw = (const float*)d_in[2];   // [64,128]
  const float* pb = (const float*)d_in[3];   // [64]
  float* out = (float*)d_out;

  float *F0, *F1, *F2, *F3, *I0, *I1, *I2, *I3;
  cudaGetSymbolAddress((void**)&F0, g_F0);
  cudaGetSymbolAddress((void**)&F1, g_F1);
  cudaGetSymbolAddress((void**)&F2, g_F2);
  cudaGetSymbolAddress((void**)&F3, g_F3);
  cudaGetSymbolAddress((void**)&I0, g_I0);
  cudaGetSymbolAddress((void**)&I1, g_I1);
  cudaGetSymbolAddress((void**)&I2, g_I2);
  cudaGetSymbolAddress((void**)&I3, g_I3);

  size_t o0 = 0;
  size_t o1 = o0 + (size_t)8 * 25600 * 81;
  size_t o2 = o1 + (size_t)8 * 6400 * 25;
  size_t o3 = o2 + (size_t)8 * 1600 * 9;

  wtrans_kernel<<<32, 256>>>(pw);                                     // 1

  proj_kernel<<<dim3(HW0 / 128, 10), 256>>>(qf, vf, pb);              // 2

  int t1 = 640 * 80 * 40;
  pool_kernel<<<(t1 + 255) / 256, 256>>>(F0, F1, 160, 160, t1);       // 3

  corr_kernel<4, 3><<<dim3(5, 40, 8), 288>>>(F0, I0, out + o0, 160, 160);  // 4 (ncu)

  int t2 = 640 * 40 * 20;
  pool_kernel<<<(t2 + 255) / 256, 256>>>(F1, F2, 80, 80, t2);         // 5
  int t3 = 640 * 20 * 10;
  pool_kernel<<<(t3 + 255) / 256, 256>>>(F2, F3, 40, 40, t3);         // 6

  int n1 = 10 * 6400, n2 = 10 * 1600, n3 = 10 * 400;
  invnorm_kernel<<<(n1 + 255) / 256, 256>>>(F1, I1, 6400, n1);        // 7
  invnorm_kernel<<<(n2 + 255) / 256, 256>>>(F2, I2, 1600, n2);        // 8
  invnorm_kernel<<<(n3 + 255) / 256, 256>>>(F3, I3, 400, n3);         // 9

  corr_kernel<2, 6><<<dim3(3, 20, 8), 160>>>(F1, I1, out + o1, 80, 80);
  corr_kernel<1, 6><<<dim3(2, 10, 8), 96>>>(F2, I2, out + o2, 40, 40);
  corr_kernel<1, 6><<<dim3(1, 5, 8), 96>>>(F3, I3, out + o3, 20, 20);
}

// round 15
// speedup vs baseline: 1.3779x; 1.3779x over previous
#include <cuda_runtime.h>

// ---------------------------------------------------------------------------
// CorrelationPyramid: proj(1x1 conv C=128->64) -> pyramid avg-pool ->
// L2-normalized banded circular correlation at 4 levels.
// Scratch features channel-planar [img][c][h][w]; img 0..1 = q batches,
// 2..9 = v (b*4+n). Normalization folded into epilogue via inverse norms.
// R14: R13 (precomputed staging addresses, no div/mod in hot path) with the
// q-staging fixed for NT<128 blocks (R=1 had unstaged rows -> wrong output).
// ---------------------------------------------------------------------------

#define HW0 25600   // 160*160

typedef unsigned long long u64;

__device__ float g_F0[10 * 64 * 25600];
__device__ float g_F1[10 * 64 * 6400];
__device__ float g_F2[10 * 64 * 1600];
__device__ float g_F3[10 * 64 * 400];
__device__ float g_I0[10 * 25600];
__device__ float g_I1[10 * 6400];
__device__ float g_I2[10 * 1600];
__device__ float g_I3[10 * 400];
__device__ __align__(16) float g_Wt[8192];   // Wt[c*64+o] = pw[o*128+c]

__device__ __forceinline__ u64 pack2(float lo, float hi) {
  u64 r;
  asm("mov.b64 %0, {%1, %2};" : "=l"(r) : "f"(lo), "f"(hi));
  return r;
}
__device__ __forceinline__ float2 unpack2(u64 v) {
  float2 f;
  asm("mov.b64 {%0, %1}, %2;" : "=f"(f.x), "=f"(f.y) : "l"(v));
  return f;
}
__device__ __forceinline__ void ffma2(u64& d, u64 a, u64 b) {
  asm("fma.rn.f32x2 %0, %1, %2, %0;" : "+l"(d) : "l"(a), "l"(b));
}

// ---------------------------------------------------------------------------
// One-off W transpose (32 KB): strided read, coalesced write. Runs once.
// ---------------------------------------------------------------------------
__global__ void wtrans_kernel(const float* __restrict__ pw) {
  int i = blockIdx.x * 256 + threadIdx.x;   // 8192 threads
  g_Wt[i] = pw[(i & 63) * 128 + (i >> 6)];
}

// ---------------------------------------------------------------------------
// Projection + fused level-0 inverse-norm (FFMA2 on output pairs).
// W read in the mainloop via uniform-address __ldg broadcasts.
// ---------------------------------------------------------------------------
__global__ __launch_bounds__(256, 3) void proj_kernel(
    const float* __restrict__ qf, const float* __restrict__ vf,
    const float* __restrict__ pb) {
  __shared__ float Bsh[64];
  __shared__ __align__(16) float Xs[16][128];

  const int img = blockIdx.y;
  const float* src = (img < 2) ? qf + (size_t)img * 128 * HW0
                               : vf + (size_t)(img - 2) * 128 * HW0;
  float* dst = g_F0 + (size_t)img * 64 * HW0;

  const int t = threadIdx.x;
  if (t < 64) Bsh[t] = pb[t];

  const int og = t >> 5;
  const int lane = t & 31;
  const int pxb = blockIdx.x * 128;
  const int px = lane * 4;

  u64 acc2[4][4];
#pragma unroll
  for (int o = 0; o < 4; o++)
#pragma unroll
    for (int i = 0; i < 4; i++) acc2[o][i] = 0ull;

  float4 pre[2];
  {
    int i0 = t * 2, i1 = t * 2 + 1;
    pre[0] = *reinterpret_cast<const float4*>(
        src + (size_t)(i0 >> 5) * HW0 + pxb + (i0 & 31) * 4);
    pre[1] = *reinterpret_cast<const float4*>(
        src + (size_t)(i1 >> 5) * HW0 + pxb + (i1 & 31) * 4);
  }

  for (int ch = 0; ch < 8; ch++) {
    __syncthreads();
#pragma unroll
    for (int j = 0; j < 2; j++) {
      int idx = t * 2 + j;
      *reinterpret_cast<float4*>(&Xs[idx >> 5][(idx & 31) * 4]) = pre[j];
    }
    __syncthreads();
    if (ch < 7) {
#pragma unroll
      for (int j = 0; j < 2; j++) {
        int idx = t * 2 + j;
        pre[j] = *reinterpret_cast<const float4*>(
            src + (size_t)((ch + 1) * 16 + (idx >> 5)) * HW0 + pxb + (idx & 31) * 4);
      }
    }
#pragma unroll
    for (int c = 0; c < 16; c++) {
      const ulonglong2* wp = reinterpret_cast<const ulonglong2*>(
          g_Wt + (ch * 16 + c) * 64 + og * 8);
      ulonglong2 wA = __ldg(wp);
      ulonglong2 wB = __ldg(wp + 1);
      float4 x = *reinterpret_cast<const float4*>(&Xs[c][px]);
      u64 xp[4] = {pack2(x.x, x.x), pack2(x.y, x.y), pack2(x.z, x.z),
                   pack2(x.w, x.w)};
#pragma unroll
      for (int i = 0; i < 4; i++) {
        ffma2(acc2[0][i], wA.x, xp[i]);
        ffma2(acc2[1][i], wA.y, xp[i]);
        ffma2(acc2[2][i], wB.x, xp[i]);
        ffma2(acc2[3][i], wB.y, xp[i]);
      }
    }
  }

  float ps[4] = {0.f, 0.f, 0.f, 0.f};
#pragma unroll
  for (int o2 = 0; o2 < 4; o2++) {
    int o0 = og * 8 + 2 * o2;
    float b0 = Bsh[o0], b1 = Bsh[o0 + 1];
    float y0[4], y1[4];
#pragma unroll
    for (int i = 0; i < 4; i++) {
      float2 y = unpack2(acc2[o2][i]);
      y0[i] = y.x + b0;
      y1[i] = y.y + b1;
      ps[i] += y0[i] * y0[i] + y1[i] * y1[i];
    }
    float4 r0 = {y0[0], y0[1], y0[2], y0[3]};
    float4 r1 = {y1[0], y1[1], y1[2], y1[3]};
    *reinterpret_cast<float4*>(dst + (size_t)o0 * HW0 + pxb + px) = r0;
    *reinterpret_cast<float4*>(dst + (size_t)(o0 + 1) * HW0 + pxb + px) = r1;
  }

  float* red = &Xs[0][0];
  __syncthreads();
  *reinterpret_cast<float4*>(&red[og * 128 + px]) =
      make_float4(ps[0], ps[1], ps[2], ps[3]);
  __syncthreads();
  if (t < 128) {
    float s = 0.f;
#pragma unroll
    for (int w = 0; w < 8; w++) s += red[w * 128 + t];
    g_I0[(size_t)img * HW0 + pxb + t] = 1.f / fmaxf(sqrtf(s), 1e-12f);
  }
}

// ---------------------------------------------------------------------------
// 2x2 avg pool.
// ---------------------------------------------------------------------------
__global__ __launch_bounds__(256) void pool_kernel(
    const float* __restrict__ in, float* __restrict__ out,
    int Hin, int Win, int total2) {
  int idx = blockIdx.x * 256 + threadIdx.x;
  if (idx >= total2) return;
  int Wo = Win >> 1, Ho = Hin >> 1;
  int w2 = Wo >> 1;
  int x2 = idx % w2;
  int rest = idx / w2;
  int y = rest % Ho;
  int plane = rest / Ho;
  const float* p = in + (size_t)plane * Hin * Win + (size_t)(2 * y) * Win + 4 * x2;
  float4 a = *reinterpret_cast<const float4*>(p);
  float4 b = *reinterpret_cast<const float4*>(p + Win);
  float2 o;
  o.x = 0.25f * (a.x + a.y + b.x + b.y);
  o.y = 0.25f * (a.z + a.w + b.z + b.w);
  *reinterpret_cast<float2*>(out + (size_t)plane * Ho * Wo + (size_t)y * Wo + 2 * x2) = o;
}

// ---------------------------------------------------------------------------
// Per-pixel inverse L2 norm over 64 channels (levels 1..3).
// ---------------------------------------------------------------------------
__global__ __launch_bounds__(256) void invnorm_kernel(
    const float* __restrict__ F, float* __restrict__ I, int HW, int total) {
  int idx = blockIdx.x * 256 + threadIdx.x;
  if (idx >= total) return;
  int img = idx / HW;
  int p = idx - img * HW;
  const float* f = F + (size_t)img * 64 * HW + p;
  float s = 0.f;
#pragma unroll
  for (int c = 0; c < 64; c++) {
    float v = f[(size_t)c * HW];
    s += v * v;
  }
  I[idx] = 1.f / fmaxf(sqrtf(s), 1e-12f);
}

// ---------------------------------------------------------------------------
// Banded circular correlation, radius R.
// Tile: 4 rows x 32 cols. Block: NW warps (warp <-> dy). Thread: 4 px x NW dx.
// ALL staging addresses precomputed once per thread; stage loops are pure
// pointer-increment LDG->STS. q staging handles NT<128 via QPOS slots.
// ---------------------------------------------------------------------------
template <int R, int MINB>
__global__ __launch_bounds__(32 * (2 * R + 1), MINB) void corr_kernel(
    const float* __restrict__ F, const float* __restrict__ I,
    float* __restrict__ out, int H, int W) {
  constexpr int NW = 2 * R + 1;
  constexpr int VW = ((32 + 2 * R + 7) & ~3);
  constexpr int VH = 4 + 2 * R;
  constexpr int VSZ = VH * VW;
  constexpr int NV4 = (4 + 2 * R + 3) / 4;
  constexpr int NT = NW * 32;
  constexpr int NPOS = (VSZ + NT - 1) / NT;
  constexpr int QPOS = (128 + NT - 1) / NT;   // q slots per thread (2 for R=1)

  __shared__ __align__(16) float qs[16][128];
  __shared__ __align__(16) float vs[16][VSZ];
  __shared__ float ivs[VSZ];

  const int bn = blockIdx.z;
  const int b = bn >> 2;
  const int HWl = H * W;
  const float* Fq = F + (size_t)b * 64 * HWl;
  const float* Fv = F + (size_t)(2 + bn) * 64 * HWl;
  const float* Iq = I + (size_t)b * HWl;
  const float* Iv = I + (size_t)(2 + bn) * HWl;

  const int tx = blockIdx.x * 32, ty = blockIdx.y * 4;
  const int t = threadIdx.x, lane = t & 31, warp = t >> 5;
  const int dy = warp - R;
  const int prow = lane >> 3;         // 0..3
  const int pc = (lane & 7) * 4;      // 0,4,..,28
  const int vr = prow + R - dy;

  // ---- one-time precompute of staging positions / wrapped offsets ----
  int vidx[NPOS], voff[NPOS];
#pragma unroll
  for (int j = 0; j < NPOS; j++) {
    int i = t + j * NT;
    if (i < VSZ) {
      int r = i / VW, c = i - r * VW;          // once per kernel, not per stage
      int h = ty + r - R; if (h < 0) h += H; if (h >= H) h -= H;
      int w = tx + c - R; if (w < 0) w += W; if (w >= W) w -= W;
      vidx[j] = i;
      voff[j] = h * W + w;
    } else {
      vidx[j] = -1;
      voff[j] = 0;
    }
  }
#pragma unroll
  for (int j = 0; j < NPOS; j++)
    if (vidx[j] >= 0) ivs[vidx[j]] = Iv[voff[j]];

  int qidx[QPOS], qoff[QPOS];
#pragma unroll
  for (int j = 0; j < QPOS; j++) {
    int i = t + j * NT;
    if (i < 128) {
      int col = i & 31, r = i >> 5;
      int w = tx + col;
      qidx[j] = i;
      qoff[j] = (w < W) ? (ty + r) * W + w : -1;
    } else {
      qidx[j] = -1;
      qoff[j] = -1;
    }
  }

  float acc[4][NW];
#pragma unroll
  for (int i = 0; i < 4; i++)
#pragma unroll
    for (int k = 0; k < NW; k++) acc[i][k] = 0.f;

  for (int st = 0; st < 4; st++) {
    __syncthreads();
    // q stage: QPOS slots per thread, 16 channel loads each by stride
#pragma unroll
    for (int j = 0; j < QPOS; j++) {
      if (qidx[j] >= 0) {
        if (qoff[j] >= 0) {
          const float* s = Fq + (size_t)(st * 16) * HWl + qoff[j];
#pragma unroll
          for (int c = 0; c < 16; c++) qs[c][qidx[j]] = s[(size_t)c * HWl];
        } else {
#pragma unroll
          for (int c = 0; c < 16; c++) qs[c][qidx[j]] = 0.f;
        }
      }
    }
    // v stage: NPOS halo slots per thread; 16 channel loads each by stride
#pragma unroll
    for (int j = 0; j < NPOS; j++) {
      if (vidx[j] >= 0) {
        const float* s = Fv + (size_t)(st * 16) * HWl + voff[j];
#pragma unroll
        for (int c = 0; c < 16; c++) vs[c][vidx[j]] = s[(size_t)c * HWl];
      }
    }
    __syncthreads();

#pragma unroll
    for (int c = 0; c < 16; c++) {
      float4 q = *reinterpret_cast<const float4*>(&qs[c][(prow << 5) + pc]);
      float qa[4] = {q.x, q.y, q.z, q.w};
      float vwin[NV4 * 4];
#pragma unroll
      for (int j = 0; j < NV4; j++)
        *reinterpret_cast<float4*>(&vwin[4 * j]) =
            *reinterpret_cast<const float4*>(&vs[c][vr * VW + pc + 4 * j]);
#pragma unroll
      for (int k = 0; k < NW; k++) {
#pragma unroll
        for (int i = 0; i < 4; i++)
          acc[i][k] += qa[i] * vwin[i + 2 * R - k];
      }
    }
  }

  const int h = ty + prow;
#pragma unroll
  for (int i = 0; i < 4; i++) {
    const int w = tx + pc + i;
    if (w >= W) continue;
    const float qi = Iq[h * W + w];
    float* op = out + ((size_t)(bn * H + h) * W + w) * (NW * NW) + (dy + R) * NW;
#pragma unroll
    for (int k = 0; k < NW; k++)
      op[k] = acc[i][k] * qi * ivs[vr * VW + pc + i + 2 * R - k];
  }
}

// ---------------------------------------------------------------------------

extern "C" void kernel_launch(void* const* d_in, const int* in_sizes, int n_in,
                              void* d_out, int out_size) {
  const float* qf = (const float*)d_in[0];   // [2,128,160,160]
  const float* vf = (const float*)d_in[1];   // [2,4,128,160,160]
  const float* pw = (const float*)d_in[2];   // [64,128]
  const float* pb = (const float*)d_in[3];   // [64]
  float* out = (float*)d_out;

  float *F0, *F1, *F2, *F3, *I0, *I1, *I2, *I3;
  cudaGetSymbolAddress((void**)&F0, g_F0);
  cudaGetSymbolAddress((void**)&F1, g_F1);
  cudaGetSymbolAddress((void**)&F2, g_F2);
  cudaGetSymbolAddress((void**)&F3, g_F3);
  cudaGetSymbolAddress((void**)&I0, g_I0);
  cudaGetSymbolAddress((void**)&I1, g_I1);
  cudaGetSymbolAddress((void**)&I2, g_I2);
  cudaGetSymbolAddress((void**)&I3, g_I3);

  size_t o0 = 0;
  size_t o1 = o0 + (size_t)8 * 25600 * 81;
  size_t o2 = o1 + (size_t)8 * 6400 * 25;
  size_t o3 = o2 + (size_t)8 * 1600 * 9;

  wtrans_kernel<<<32, 256>>>(pw);                                     // 1

  proj_kernel<<<dim3(HW0 / 128, 10), 256>>>(qf, vf, pb);              // 2

  int t1 = 640 * 80 * 40;
  pool_kernel<<<(t1 + 255) / 256, 256>>>(F0, F1, 160, 160, t1);       // 3

  corr_kernel<4, 3><<<dim3(5, 40, 8), 288>>>(F0, I0, out + o0, 160, 160);  // 4 (ncu)

  int t2 = 640 * 40 * 20;
  pool_kernel<<<(t2 + 255) / 256, 256>>>(F1, F2, 80, 80, t2);         // 5
  int t3 = 640 * 20 * 10;
  pool_kernel<<<(t3 + 255) / 256, 256>>>(F2, F3, 40, 40, t3);         // 6

  int n1 = 10 * 6400, n2 = 10 * 1600, n3 = 10 * 400;
  invnorm_kernel<<<(n1 + 255) / 256, 256>>>(F1, I1, 6400, n1);        // 7
  invnorm_kernel<<<(n2 + 255) / 256, 256>>>(F2, I2, 1600, n2);        // 8
  invnorm_kernel<<<(n3 + 255) / 256, 256>>>(F3, I3, 400, n3);         // 9

  corr_kernel<2, 6><<<dim3(3, 20, 8), 160>>>(F1, I1, out + o1, 80, 80);
  corr_kernel<1, 6><<<dim3(2, 10, 8), 96>>>(F2, I2, out + o2, 40, 40);
  corr_kernel<1, 6><<<dim3(1, 5, 8), 96>>>(F3, I3, out + o3, 20, 20);
}